// round 11
// baseline (speedup 1.0000x reference)
#include <cuda_runtime.h>
#include <math.h>

// Problem constants
#define BGR   128
#define N0    1024
#define NTOT  131072
#define ETOT  2097152
#define EPG   16384
#define DD    64
#define K1    820
#define K2    656
#define K3    525

#define NEG_INF __int_as_float(0xff800000)

// ---------------- scratch ---------------------------------------------------
__device__ float g_x[NTOT * DD];
__device__ float g_y[NTOT * DD];
__device__ float g_msg[NTOT * DD];
__device__ float g_aggr[NTOT * DD];
__device__ float g_score[NTOT];
__device__ int   g_selold[NTOT];
__device__ float g_selscale[NTOT];
__device__ int   g_inv[NTOT];
__device__ int   g_esrc[2][ETOT];     // -1 sentinel = invalid edge
__device__ int   g_edst[2][ETOT];
__device__ float g_h[BGR * 2 * DD];
// CSR scratch (layer 3)
__device__ int   g_deg[NTOT];
__device__ int   g_headp[NTOT];
__device__ int   g_cur[NTOT];
__device__ int   g_csr[ETOT];
// combo / LUT scratch; combos compressed to 0..31
__device__ int      g_mask1[NTOT];
__device__ int      g_combo2[NTOT];
__device__ unsigned g_pres2[NTOT];
__device__ float g_sc1lut[32];
__device__ float g_x2lut[32 * 64];
__device__ float g_msg2lut[32 * 64];
__device__ float g_x2part[32 * 64];
__device__ float g_cmax[4 * 256 * 64];

// ---------------- helpers ----------------------------------------------------

__device__ __forceinline__ unsigned long long packkey(float s, int idx) {
    unsigned u = __float_as_uint(s);
    u = (u & 0x80000000u) ? ~u : (u | 0x80000000u);
    unsigned hi = ~u;
    return ((unsigned long long)hi << 32) | (unsigned)idx;
}

__device__ __forceinline__ void bitonic1024(unsigned long long& key,
                                            unsigned long long* sk, int t) {
    for (int ksz = 2; ksz <= 1024; ksz <<= 1) {
        for (int j = ksz >> 1; j >= 32; j >>= 1) {
            sk[t] = key;
            __syncthreads();
            unsigned long long o = sk[t ^ j];
            bool keepmin = (((t & j) == 0) == ((t & ksz) == 0));
            key = (keepmin == (o < key)) ? o : key;
            __syncthreads();
        }
        int jmax = ((ksz >> 1) < 16) ? (ksz >> 1) : 16;
        for (int j = jmax; j >= 1; j >>= 1) {
            unsigned long long o = __shfl_xor_sync(0xffffffffu, key, j);
            bool keepmin = (((t & j) == 0) == ((t & ksz) == 0));
            key = (keepmin == (o < key)) ? o : key;
        }
    }
}

#define RELU(v) ((v) > 0.f ? (v) : 0.f)

// packed fp32x2 FMA (sm_100+): two bit-exact fp32 FMAs per instruction
__device__ __forceinline__ unsigned long long pack2(float lo, float hi) {
    unsigned long long r;
    asm("mov.b64 %0, {%1, %2};" : "=l"(r) : "f"(lo), "f"(hi));
    return r;
}
__device__ __forceinline__ void unpack2(unsigned long long v, float& lo, float& hi) {
    asm("mov.b64 {%0, %1}, %2;" : "=f"(lo), "=f"(hi) : "l"(v));
}
__device__ __forceinline__ unsigned long long ffma2(unsigned long long a,
                                                    unsigned long long b,
                                                    unsigned long long c) {
    unsigned long long d;
    asm("fma.rn.f32x2 %0, %1, %2, %3;" : "=l"(d) : "l"(a), "l"(b), "l"(c));
    return d;
}

// ---------------- init --------------------------------------------------------

__global__ void k_zero_mask() {
    int i = blockIdx.x * blockDim.x + threadIdx.x;
    if (i < NTOT) g_mask1[i] = 0;
}

// ---------------- layer-1/2 LUT machinery --------------------------------------

__device__ __forceinline__ void body_mask1(int e, const int* __restrict__ src,
                                           const int* __restrict__ dst,
                                           const int* __restrict__ x_ids) {
    if (e >= ETOT) return;
    atomicOr(&g_mask1[dst[e]], 1 << x_ids[src[e]]);
}

// All LUTs in one 256-thread block. Compressed combo cc = id*8 + m3 (32 combos).
__device__ __forceinline__ void body_lut1(
    int t,
    const float* __restrict__ emb,
    const float* __restrict__ W1, const float* __restrict__ b1,
    const float* __restrict__ U1, const float* __restrict__ p1,
    const float* __restrict__ W2, const float* __restrict__ b2,
    const float* __restrict__ U2) {
    __shared__ float s_emb[4][64], s_m1[4][64], s_amax[16][64];
    __shared__ float s_y1[32][64], s_x2[32][64];
    __shared__ float s_scale[32];
    __shared__ float s_pinv;
    s_emb[t >> 6][t & 63] = emb[t];
    if (t == 0) {
        float s = 0.f;
        for (int i = 0; i < 64; i++) s += p1[i] * p1[i];
        s_pinv = 1.0f / sqrtf(s);
    }
    __syncthreads();
    {
        int id = t >> 6, o = t & 63;
        float a = b1[o];
        for (int i = 0; i < 64; i++) a = fmaf(s_emb[id][i], W1[o * 64 + i], a);
        s_m1[id][o] = RELU(a);
    }
    __syncthreads();
    for (int u = t; u < 16 * 64; u += 256) {
        int mask = u >> 6, o = u & 63;
        float v = NEG_INF;
        for (int id = 0; id < 4; id++)
            if ((mask >> id) & 1) v = fmaxf(v, s_m1[id][o]);
        if (mask == 0) v = 0.f;
        s_amax[mask][o] = v;
    }
    __syncthreads();
    for (int u = t; u < 32 * 64; u += 256) {
        int cc = u >> 6, o = u & 63;
        int id = cc >> 3, m3 = cc & 7;
        int lower = m3 & ((1 << id) - 1);
        int upper = (m3 >> id) << (id + 1);
        int mask = lower | upper | (1 << id);
        float a = 0.f;
        for (int i = 0; i < 64; i++) a = fmaf(s_amax[mask][i], U1[o * 128 + i], a);
        for (int i = 0; i < 64; i++) a = fmaf(s_emb[id][i], U1[o * 128 + 64 + i], a);
        s_y1[cc][o] = RELU(a);
    }
    __syncthreads();
    if (t < 32) {
        float s = 0.f;
        for (int i = 0; i < 64; i++) s = fmaf(s_y1[t][i], p1[i], s);
        s *= s_pinv;
        g_sc1lut[t] = s;
        s_scale[t]  = tanhf(s);
    }
    __syncthreads();
    for (int u = t; u < 32 * 64; u += 256) {
        int cc = u >> 6, d = u & 63;
        float v = s_y1[cc][d] * s_scale[cc];
        s_x2[cc][d] = v;
        g_x2lut[u] = v;
    }
    __syncthreads();
    for (int u = t; u < 32 * 64; u += 256) {
        int cc = u >> 6, o = u & 63;
        float a = b2[o];
        for (int i = 0; i < 64; i++) a = fmaf(s_x2[cc][i], W2[o * 64 + i], a);
        g_msg2lut[u] = RELU(a);
        float x = 0.f;
        for (int i = 0; i < 64; i++) x = fmaf(s_x2[cc][i], U2[o * 128 + 64 + i], x);
        g_x2part[u] = x;
    }
}

#define EB 8192   // ETOT/256

// fused: mask1 (8192 blocks) + lut1 (1 block) — mutually independent
__global__ void __launch_bounds__(256)
k_m1lut(const int* __restrict__ src, const int* __restrict__ dst,
        const int* __restrict__ x_ids,
        const float* __restrict__ emb,
        const float* __restrict__ W1, const float* __restrict__ b1,
        const float* __restrict__ U1, const float* __restrict__ p1,
        const float* __restrict__ W2, const float* __restrict__ b2,
        const float* __restrict__ U2) {
    int blk = blockIdx.x, t = threadIdx.x;
    if (blk < EB) body_mask1(blk * 256 + t, src, dst, x_ids);
    else          body_lut1(t, emb, W1, b1, U1, p1, W2, b2, U2);
}

// ---------------- topk kernels --------------------------------------------------

__global__ void __launch_bounds__(1024)
k_topk1(const int* __restrict__ x_ids) {
    __shared__ unsigned long long sk[1024];
    __shared__ unsigned char scb[1024];
    int b = blockIdx.x, t = threadIdx.x;
    int node = b * 1024 + t;
    int id = x_ids[node];
    int mask = g_mask1[node] | (1 << id);
    int lower = mask & ((1 << id) - 1);
    int upper = (mask >> (id + 1)) << id;
    int cc = id * 8 + (lower | upper);
    scb[t] = (unsigned char)cc;
    unsigned long long key = packkey(g_sc1lut[cc], t);
    g_inv[node] = -1;
    __syncthreads();
    bitonic1024(key, sk, t);
    if (t < K1) {
        int idx = (int)(key & 0xffffffffu);
        int old = b * 1024 + idx;
        int nw  = b * K1 + t;
        g_inv[old]   = nw;
        int c = scb[idx];
        g_combo2[nw] = c;
        g_pres2[nw]  = 1u << c;
    }
}

__global__ void __launch_bounds__(1024)
k_topk(int n_per, int k, int write_inv) {
    __shared__ unsigned long long sk[1024];
    int b = blockIdx.x, t = threadIdx.x;
    unsigned long long key = 0xFFFFFFFFFFFFFFFFull;
    if (t < n_per) {
        key = packkey(g_score[b * n_per + t], t);
        if (write_inv) g_inv[b * n_per + t] = -1;
    }
    __syncthreads();
    bitonic1024(key, sk, t);
    if (t < k) {
        int idx = (int)(key & 0xffffffffu);
        int old = b * n_per + idx;
        int nw  = b * k + t;
        g_selold[nw]   = old;
        g_selscale[nw] = tanhf(g_score[old]);
        if (write_inv) g_inv[old] = nw;
    }
}

// ---------------- fused thin-kernel bodies ---------------------------------------

// raw edges -> bank 0 (ns=-1 sentinel); fused layer-2 presence OR
__device__ __forceinline__ void body_remap1(int e, const int* __restrict__ src,
                                            const int* __restrict__ dst) {
    if (e >= ETOT) return;
    int ns = g_inv[src[e]];
    int nd = g_inv[dst[e]];
    bool nm = (ns >= 0) && (nd >= 0);
    g_esrc[0][e] = nm ? ns : -1;
    g_edst[0][e] = nm ? nd : 0;
    if (nm) atomicOr(&g_pres2[nd], 1u << g_combo2[ns]);
}

// layer-1 readout via per-combo counting; FIRST writer of g_h (plain store)
__device__ __forceinline__ void body_readout1c(int b, int t) {
    __shared__ int cnt[32];
    if (t < 32) cnt[t] = 0;
    __syncthreads();
    for (int j = t; j < K1; j += 256)
        atomicAdd(&cnt[g_combo2[b * K1 + j]], 1);
    __syncthreads();
    if (t < 64) {
        float mx = NEG_INF, sm = 0.f;
        for (int c = 0; c < 32; c++) {
            int n = cnt[c];
            if (n > 0) {
                float v = g_x2lut[c * 64 + t];
                mx = fmaxf(mx, v);
                sm = fmaf((float)n, v, sm);
            }
        }
        g_h[b * 128 + t]      = mx;
        g_h[b * 128 + 64 + t] = sm / (float)K1;
    }
}

__device__ __forceinline__ void body_cmax(int i) {
    int d = i & 63;
    int v = (i >> 6) & 255;
    int ch = i >> 14;
    float m = NEG_INF;
#pragma unroll
    for (int b = 0; b < 8; b++)
        if ((v >> b) & 1) m = fmaxf(m, g_msg2lut[(ch * 8 + b) * 64 + d]);
    g_cmax[i] = m;
}

// t1 = remap1 (8192) + readout1c (128) + cmax (256) + zero_deg (512)
__global__ void __launch_bounds__(256)
k_t1(const int* __restrict__ src, const int* __restrict__ dst) {
    int blk = blockIdx.x, t = threadIdx.x;
    if (blk < EB) {
        body_remap1(blk * 256 + t, src, dst);
    } else if (blk < EB + BGR) {
        body_readout1c(blk - EB, t);
    } else if (blk < EB + BGR + 256) {
        body_cmax((blk - EB - BGR) * 256 + t);
    } else {
        int i = (blk - EB - BGR - 256) * 256 + t;
        if (i < NTOT) g_deg[i] = 0;
    }
}

// flat gather
__device__ __forceinline__ void body_gather(int idx, int nk) {
    if (idx >= nk * DD) return;
    int j = idx >> 6, d = idx & 63;
    g_x[idx] = g_y[(size_t)g_selold[j] * DD + d] * g_selscale[j];
}

// bank0 -> bank1, fused degree count
__device__ __forceinline__ void body_remap2(int e) {
    if (e >= ETOT) return;
    int s0 = g_esrc[0][e];
    int ns = -1, nd = 0;
    if (s0 >= 0) {
        ns = g_inv[s0];
        nd = g_inv[g_edst[0][e]];
        if (nd < 0) ns = -1;
        else if (ns >= 0) atomicAdd(&g_deg[nd], 1);
    }
    g_esrc[1][e] = ns;
    g_edst[1][e] = (ns >= 0) ? nd : 0;
}

#define GB2 20992   // (83968*64)/256

// t2 = gather(n3) + remap2
__global__ void __launch_bounds__(256)
k_t2(int nk) {
    int blk = blockIdx.x, t = threadIdx.x;
    if (blk < GB2) body_gather(blk * 256 + t, nk);
    else           body_remap2((blk - GB2) * 256 + t);
}

// contiguous readout over g_x (256 threads, 4 slices)
__device__ __forceinline__ void body_readout(int b, int t, int k) {
    __shared__ float smx[4][64], ssm[4][64];
    int d = t & 63, r = t >> 6;
    int per = (k + 3) / 4;
    int j0 = r * per;
    int j1 = min(k, j0 + per);
    float mx = NEG_INF, sm = 0.f;
    const float* base = g_x + (size_t)b * k * DD + d;
    for (int j = j0; j < j1; j++) {
        float v = base[(size_t)j * DD];
        mx = fmaxf(mx, v);
        sm += v;
    }
    smx[r][d] = mx; ssm[r][d] = sm;
    __syncthreads();
    if (r == 0) {
#pragma unroll
        for (int i = 1; i < 4; i++) {
            mx = fmaxf(mx, smx[i][d]);
            sm += ssm[i][d];
        }
        g_h[b * 128 + d]      += mx;
        g_h[b * 128 + 64 + d] += sm / (float)k;
    }
}

// 256-thread exclusive scan over n_per (<=1024, multiple of 4) degrees
__device__ __forceinline__ void body_scan256(int g, int t, int n_per) {
    __shared__ int wsum[8];
    int lane = t & 31, wid = t >> 5;
    int4 v = make_int4(0, 0, 0, 0);
    int base = g * n_per + t * 4;
    bool act = (t * 4 < n_per);
    if (act) v = *(const int4*)(g_deg + base);
    int s = v.x + v.y + v.z + v.w;
    int x = s;
#pragma unroll
    for (int off = 1; off < 32; off <<= 1) {
        int u = __shfl_up_sync(0xffffffffu, x, off);
        if (lane >= off) x += u;
    }
    if (lane == 31) wsum[wid] = x;
    __syncthreads();
    if (t == 0) {
        int a = 0;
#pragma unroll
        for (int i = 0; i < 8; i++) { int tmp = wsum[i]; wsum[i] = a; a += tmp; }
    }
    __syncthreads();
    if (act) {
        int h = g * EPG + wsum[wid] + (x - s);
        g_headp[base + 0] = h; g_cur[base + 0] = h; h += v.x;
        g_headp[base + 1] = h; g_cur[base + 1] = h; h += v.y;
        g_headp[base + 2] = h; g_cur[base + 2] = h; h += v.z;
        g_headp[base + 3] = h; g_cur[base + 3] = h;
    }
}

// t3 = readout(K2) (128 blocks) + scan256 (128 blocks)
__global__ void __launch_bounds__(256)
k_t3() {
    int blk = blockIdx.x, t = threadIdx.x;
    if (blk < BGR) body_readout(blk, t, K2);
    else           body_scan256(blk - BGR, t, K2);
}

__device__ __forceinline__ void body_fill(int e) {
    if (e >= ETOT) return;
    int s = g_esrc[1][e];
    if (s < 0) return;
    int d = g_edst[1][e];
    int pos = atomicAdd(&g_cur[d], 1);
    g_csr[pos] = s;
}

// standalone gather/readout for layer-3 tail
__global__ void k_gather(int nk) {
    body_gather(blockIdx.x * blockDim.x + threadIdx.x, nk);
}
__global__ void __launch_bounds__(256)
k_readout(int k) {
    body_readout(blockIdx.x, threadIdx.x, k);
}

// ---------------- aggregation ---------------------------------------------------

__global__ void k_aggr2(int n) {
    int w = (blockIdx.x * blockDim.x + threadIdx.x) >> 5;
    int lane = threadIdx.x & 31;
    if (w >= n) return;
    unsigned m = g_pres2[w];
    float m0 = NEG_INF, m1 = NEG_INF;
#pragma unroll
    for (int ch = 0; ch < 4; ch++) {
        unsigned v = (m >> (ch * 8)) & 255u;
        if (v) {
            const float* r = g_cmax + ((ch << 8) | v) * 64;
            m0 = fmaxf(m0, __ldg(r + lane));
            m1 = fmaxf(m1, __ldg(r + lane + 32));
        }
    }
    float* ar = g_aggr + (size_t)w * DD;
    ar[lane]      = m0;
    ar[lane + 32] = m1;
}

__global__ void k_aggr3(int n) {
    int w = (blockIdx.x * blockDim.x + threadIdx.x) >> 5;
    int lane = threadIdx.x & 31;
    if (w >= n) return;
    const float* mrow = g_msg + (size_t)w * DD;
    float m0 = mrow[lane];
    float m1 = mrow[lane + 32];
    int e   = g_headp[w];
    int end = g_cur[w];
    for (; e + 4 <= end; e += 4) {
        int s0 = __ldg(&g_csr[e]);
        int s1 = __ldg(&g_csr[e + 1]);
        int s2 = __ldg(&g_csr[e + 2]);
        int s3 = __ldg(&g_csr[e + 3]);
        const float* r0 = g_msg + (size_t)s0 * DD;
        const float* r1 = g_msg + (size_t)s1 * DD;
        const float* r2 = g_msg + (size_t)s2 * DD;
        const float* r3 = g_msg + (size_t)s3 * DD;
        float a0 = r0[lane], b0 = r0[lane + 32];
        float a1 = r1[lane], b1 = r1[lane + 32];
        float a2 = r2[lane], b2 = r2[lane + 32];
        float a3 = r3[lane], b3 = r3[lane + 32];
        m0 = fmaxf(fmaxf(fmaxf(m0, a0), fmaxf(a1, a2)), a3);
        m1 = fmaxf(fmaxf(fmaxf(m1, b0), fmaxf(b1, b2)), b3);
    }
    for (; e < end; e++) {
        int s0 = __ldg(&g_csr[e]);
        const float* r0 = g_msg + (size_t)s0 * DD;
        m0 = fmaxf(m0, r0[lane]);
        m1 = fmaxf(m1, r0[lane + 32]);
    }
    float* ar = g_aggr + (size_t)w * DD;
    ar[lane]      = m0;
    ar[lane + 32] = m1;
}

// ---------------- GEMMs (f32x2 FMA + LDS.128 weights + float4 row I/O) -------------

__device__ __forceinline__ void body_gemm64(int row,
                                            const float (*Wt)[64],
                                            const float* __restrict__ bias, int n) {
    if (row >= n) return;
    const float4* xr4 = (const float4*)(g_x + (size_t)row * DD);
    unsigned long long acc[32];
#pragma unroll
    for (int o = 0; o < 32; o++) acc[o] = pack2(bias[2 * o], bias[2 * o + 1]);
#pragma unroll
    for (int c = 0; c < 4; c++) {
        float4 v0 = xr4[c * 4 + 0], v1 = xr4[c * 4 + 1];
        float4 v2 = xr4[c * 4 + 2], v3 = xr4[c * 4 + 3];
        float xv[16] = {v0.x, v0.y, v0.z, v0.w, v1.x, v1.y, v1.z, v1.w,
                        v2.x, v2.y, v2.z, v2.w, v3.x, v3.y, v3.z, v3.w};
#pragma unroll
        for (int ii = 0; ii < 16; ii++) {
            int i = c * 16 + ii;
            unsigned long long xv2 = pack2(xv[ii], xv[ii]);
            const ulonglong2* wt4 = (const ulonglong2*)&Wt[i][0];
#pragma unroll
            for (int o = 0; o < 16; o++) {
                ulonglong2 w2 = wt4[o];
                acc[o * 2 + 0] = ffma2(xv2, w2.x, acc[o * 2 + 0]);
                acc[o * 2 + 1] = ffma2(xv2, w2.y, acc[o * 2 + 1]);
            }
        }
    }
    float4* mr4 = (float4*)(g_msg + (size_t)row * DD);
#pragma unroll
    for (int c = 0; c < 16; c++) {
        float a0, a1, a2, a3;
        unpack2(acc[c * 2 + 0], a0, a1);
        unpack2(acc[c * 2 + 1], a2, a3);
        float4 w;
        w.x = RELU(a0); w.y = RELU(a1); w.z = RELU(a2); w.w = RELU(a3);
        mr4[c] = w;
    }
}

#define GB3 656   // (83968+127)/128

// fused: gemm64 (656 blocks x 128) + fill (16384 blocks x 128)
__global__ void __launch_bounds__(128)
k_l3a(const float* __restrict__ W, const float* __restrict__ bias, int n) {
    __shared__ __align__(16) float Wt[64][64];
    int blk = blockIdx.x, t = threadIdx.x;
    if (blk < GB3) {
        for (int u = t; u < 64 * 64; u += 128) {
            int o = u >> 6, i = u & 63;
            Wt[i][o] = W[u];
        }
        __syncthreads();
        body_gemm64(blk * 128 + t, Wt, bias, n);
    } else {
        body_fill((blk - GB3) * 128 + t);
    }
}

// layer-2: y = relu(aggr @ Ua^T + x2part[combo]); fused score
__global__ void __launch_bounds__(128)
k_gemmcat2(const float* __restrict__ U, const float* __restrict__ p, int n) {
    __shared__ __align__(16) float Ut[64][64];
    __shared__ __align__(16) float x2p[32][64];
    __shared__ float ps[64];
    __shared__ float pinv;
    for (int t = threadIdx.x; t < 64 * 64; t += blockDim.x) {
        int o = t >> 6, i = t & 63;
        Ut[i][o] = U[o * 128 + i];
    }
    for (int t = threadIdx.x; t < 32 * 64; t += blockDim.x)
        x2p[t >> 6][t & 63] = g_x2part[t];
    if (threadIdx.x < 64) ps[threadIdx.x] = p[threadIdx.x];
    __syncthreads();
    if (threadIdx.x == 0) {
        float s = 0.f;
        for (int i = 0; i < 64; i++) s += ps[i] * ps[i];
        pinv = 1.0f / sqrtf(s);
    }
    __syncthreads();
    int row = blockIdx.x * blockDim.x + threadIdx.x;
    if (row >= n) return;
    int cmb = g_combo2[row];
    const float4* ar4 = (const float4*)(g_aggr + (size_t)row * DD);
    const unsigned long long* xp2 = (const unsigned long long*)&x2p[cmb][0];
    unsigned long long acc[32];
#pragma unroll
    for (int o = 0; o < 32; o++) acc[o] = xp2[o];
#pragma unroll
    for (int c = 0; c < 4; c++) {
        float4 v0 = ar4[c * 4 + 0], v1 = ar4[c * 4 + 1];
        float4 v2 = ar4[c * 4 + 2], v3 = ar4[c * 4 + 3];
        float av[16] = {v0.x, v0.y, v0.z, v0.w, v1.x, v1.y, v1.z, v1.w,
                        v2.x, v2.y, v2.z, v2.w, v3.x, v3.y, v3.z, v3.w};
#pragma unroll
        for (int ii = 0; ii < 16; ii++) {
            int i = c * 16 + ii;
            unsigned long long av2 = pack2(av[ii], av[ii]);
            const ulonglong2* ut4 = (const ulonglong2*)&Ut[i][0];
#pragma unroll
            for (int o = 0; o < 16; o++) {
                ulonglong2 w2 = ut4[o];
                acc[o * 2 + 0] = ffma2(av2, w2.x, acc[o * 2 + 0]);
                acc[o * 2 + 1] = ffma2(av2, w2.y, acc[o * 2 + 1]);
            }
        }
    }
    float4* yr4 = (float4*)(g_y + (size_t)row * DD);
    float sc = 0.f;
#pragma unroll
    for (int c = 0; c < 16; c++) {
        float a0, a1, a2, a3;
        unpack2(acc[c * 2 + 0], a0, a1);
        unpack2(acc[c * 2 + 1], a2, a3);
        float4 w;
        w.x = RELU(a0); w.y = RELU(a1); w.z = RELU(a2); w.w = RELU(a3);
        yr4[c] = w;
        sc = fmaf(w.x, ps[c * 4 + 0], sc);
        sc = fmaf(w.y, ps[c * 4 + 1], sc);
        sc = fmaf(w.z, ps[c * 4 + 2], sc);
        sc = fmaf(w.w, ps[c * 4 + 3], sc);
    }
    g_score[row] = sc * pinv;
}

// layer-3 full concat GEMM + fused score
__global__ void __launch_bounds__(128)
k_gemmcat(const float* __restrict__ U, const float* __restrict__ p, int n) {
    __shared__ __align__(16) float Ut[128][64];
    __shared__ float ps[64];
    __shared__ float pinv;
    for (int t = threadIdx.x; t < 128 * 64; t += blockDim.x) {
        int o = t >> 7, i = t & 127;
        Ut[i][o] = U[t];
    }
    if (threadIdx.x < 64) ps[threadIdx.x] = p[threadIdx.x];
    __syncthreads();
    if (threadIdx.x == 0) {
        float s = 0.f;
        for (int i = 0; i < 64; i++) s += ps[i] * ps[i];
        pinv = 1.0f / sqrtf(s);
    }
    __syncthreads();
    int row = blockIdx.x * blockDim.x + threadIdx.x;
    if (row >= n) return;
    const float4* ar4 = (const float4*)(g_aggr + (size_t)row * DD);
    const float4* xr4 = (const float4*)(g_x   + (size_t)row * DD);
    unsigned long long acc[32];
#pragma unroll
    for (int o = 0; o < 32; o++) acc[o] = 0ull;
#pragma unroll
    for (int c = 0; c < 4; c++) {
        float4 v0 = ar4[c * 4 + 0], v1 = ar4[c * 4 + 1];
        float4 v2 = ar4[c * 4 + 2], v3 = ar4[c * 4 + 3];
        float av[16] = {v0.x, v0.y, v0.z, v0.w, v1.x, v1.y, v1.z, v1.w,
                        v2.x, v2.y, v2.z, v2.w, v3.x, v3.y, v3.z, v3.w};
#pragma unroll
        for (int ii = 0; ii < 16; ii++) {
            int i = c * 16 + ii;
            unsigned long long av2 = pack2(av[ii], av[ii]);
            const ulonglong2* ut4 = (const ulonglong2*)&Ut[i][0];
#pragma unroll
            for (int o = 0; o < 16; o++) {
                ulonglong2 w2 = ut4[o];
                acc[o * 2 + 0] = ffma2(av2, w2.x, acc[o * 2 + 0]);
                acc[o * 2 + 1] = ffma2(av2, w2.y, acc[o * 2 + 1]);
            }
        }
    }
#pragma unroll
    for (int c = 0; c < 4; c++) {
        float4 v0 = xr4[c * 4 + 0], v1 = xr4[c * 4 + 1];
        float4 v2 = xr4[c * 4 + 2], v3 = xr4[c * 4 + 3];
        float xv[16] = {v0.x, v0.y, v0.z, v0.w, v1.x, v1.y, v1.z, v1.w,
                        v2.x, v2.y, v2.z, v2.w, v3.x, v3.y, v3.z, v3.w};
#pragma unroll
        for (int ii = 0; ii < 16; ii++) {
            int i = 64 + c * 16 + ii;
            unsigned long long xv2 = pack2(xv[ii], xv[ii]);
            const ulonglong2* ut4 = (const ulonglong2*)&Ut[i][0];
#pragma unroll
            for (int o = 0; o < 16; o++) {
                ulonglong2 w2 = ut4[o];
                acc[o * 2 + 0] = ffma2(xv2, w2.x, acc[o * 2 + 0]);
                acc[o * 2 + 1] = ffma2(xv2, w2.y, acc[o * 2 + 1]);
            }
        }
    }
    float4* yr4 = (float4*)(g_y + (size_t)row * DD);
    float sc = 0.f;
#pragma unroll
    for (int c = 0; c < 16; c++) {
        float a0, a1, a2, a3;
        unpack2(acc[c * 2 + 0], a0, a1);
        unpack2(acc[c * 2 + 1], a2, a3);
        float4 w;
        w.x = RELU(a0); w.y = RELU(a1); w.z = RELU(a2); w.w = RELU(a3);
        yr4[c] = w;
        sc = fmaf(w.x, ps[c * 4 + 0], sc);
        sc = fmaf(w.y, ps[c * 4 + 1], sc);
        sc = fmaf(w.z, ps[c * 4 + 2], sc);
        sc = fmaf(w.w, ps[c * 4 + 3], sc);
    }
    g_score[row] = sc * pinv;
}

// ---------------- head ------------------------------------------------------------

__global__ void k_mlp(const float* __restrict__ l1W, const float* __restrict__ l1b,
                      const float* __restrict__ l2W, const float* __restrict__ l2b,
                      const float* __restrict__ l3W, const float* __restrict__ l3b,
                      float* __restrict__ out, int out_size) {
    int b = blockIdx.x;
    int o = threadIdx.x;   // 64
    __shared__ float h[128], s1[64], s2[64];
    h[o]      = g_h[b * 128 + o];
    h[o + 64] = g_h[b * 128 + 64 + o];
    __syncthreads();
    float a = l1b[o];
#pragma unroll 8
    for (int i = 0; i < 128; i++) a = fmaf(h[i], l1W[o * 128 + i], a);
    s1[o] = fmaxf(a, 0.f);
    __syncthreads();
    a = l2b[o];
#pragma unroll 8
    for (int i = 0; i < 64; i++) a = fmaf(s1[i], l2W[o * 64 + i], a);
    s2[o] = fmaxf(a, 0.f);
    __syncthreads();
    a = l3b[o];
#pragma unroll 8
    for (int i = 0; i < 64; i++) a = fmaf(s2[i], l3W[o * 64 + i], a);
    out[b * 64 + o] = 1.f / (1.f + expf(-a));
    for (int i = o; i < K3; i += 64) {
        int pos = 8192 + b * K3 + i;
        if (pos < out_size) out[pos] = (float)b;
    }
}

// ---------------- host orchestration ----------------------------------------------

extern "C" void kernel_launch(void* const* d_in, const int* in_sizes, int n_in,
                              void* d_out, int out_size) {
    const int*   x_ids = (const int*)d_in[0];
    const int*   eidx  = (const int*)d_in[1];
    const float* emb   = (const float*)d_in[2];
    const float* W1 = (const float*)d_in[3];
    const float* b1 = (const float*)d_in[4];
    const float* U1 = (const float*)d_in[5];
    const float* p1 = (const float*)d_in[6];
    const float* W2 = (const float*)d_in[7];
    const float* b2 = (const float*)d_in[8];
    const float* U2 = (const float*)d_in[9];
    const float* p2 = (const float*)d_in[10];
    const float* W3 = (const float*)d_in[11];
    const float* b3 = (const float*)d_in[12];
    const float* U3 = (const float*)d_in[13];
    const float* p3 = (const float*)d_in[14];
    const float* l1W = (const float*)d_in[15];
    const float* l1b = (const float*)d_in[16];
    const float* l2W = (const float*)d_in[17];
    const float* l2b = (const float*)d_in[18];
    const float* l3W = (const float*)d_in[19];
    const float* l3b = (const float*)d_in[20];
    float* out = (float*)d_out;

    const int n2 = BGR * K1;   // 104960
    const int n3 = BGR * K2;   // 83968

    // ---- layer 1 ----
    k_zero_mask<<<(NTOT + 255) / 256, 256>>>();
    k_m1lut<<<EB + 1, 256>>>(eidx, eidx + ETOT, x_ids,
                             emb, W1, b1, U1, p1, W2, b2, U2);
    k_topk1<<<BGR, 1024>>>(x_ids);
    k_t1<<<EB + BGR + 256 + 512, 256>>>(eidx, eidx + ETOT);

    // ---- layer 2 ----
    k_aggr2<<<(n2 * 32 + 255) / 256, 256>>>(n2);
    k_gemmcat2<<<(n2 + 127) / 128, 128>>>(U2, p2, n2);
    k_topk<<<BGR, 1024>>>(K1, K2, 1);
    k_t2<<<GB2 + EB, 256>>>(n3);                 // gather(n3) + remap2
    k_t3<<<BGR * 2, 256>>>();                    // readout(K2) + scan256

    // ---- layer 3 ----
    k_l3a<<<GB3 + ETOT / 128, 128>>>(W3, b3, n3);   // gemm64 + fill
    k_aggr3<<<(n3 * 32 + 255) / 256, 256>>>(n3);
    k_gemmcat<<<(n3 + 127) / 128, 128>>>(U3, p3, n3);
    k_topk<<<BGR, 1024>>>(K2, K3, 0);
    int nk3 = BGR * K3;
    k_gather<<<(nk3 * DD + 255) / 256, 256>>>(nk3);
    k_readout<<<BGR, 256>>>(K3);

    // ---- head ----
    k_mlp<<<BGR, 64>>>(l1W, l1b, l2W, l2b, l3W, l3b, out, out_size);
}

// round 12
// speedup vs baseline: 1.1214x; 1.1214x over previous
#include <cuda_runtime.h>
#include <math.h>

// Problem constants
#define BGR   128
#define N0    1024
#define NTOT  131072
#define ETOT  2097152
#define EPG   16384
#define DD    64
#define K1    820
#define K2    656
#define K3    525

#define NEG_INF __int_as_float(0xff800000)

// ---------------- scratch ---------------------------------------------------
__device__ float g_x[NTOT * DD];
__device__ float g_y[NTOT * DD];
__device__ float g_msg[NTOT * DD];
__device__ float g_aggr[NTOT * DD];
__device__ float g_score[NTOT];
__device__ int   g_selold[NTOT];
__device__ float g_selscale[NTOT];
__device__ int   g_inv[NTOT];
__device__ int   g_esrc[2][ETOT];     // -1 sentinel = invalid edge
__device__ int   g_edst[2][ETOT];
__device__ float g_h[BGR * 2 * DD];
// CSR scratch (layer 3)
__device__ int   g_deg[NTOT];
__device__ int   g_headp[NTOT];
__device__ int   g_cur[NTOT];
__device__ int   g_csr[ETOT];
// combo / LUT scratch; combos compressed to 0..31
__device__ int      g_mask1[NTOT];
__device__ int      g_combo2[NTOT];
__device__ unsigned g_pres2[NTOT];
__device__ float g_sc1lut[32];
__device__ float g_x2lut[32 * 64];
__device__ float g_msg2lut[32 * 64];
__device__ float g_x2part[32 * 64];
__device__ float g_cmax[4 * 256 * 64];

// ---------------- helpers ----------------------------------------------------

__device__ __forceinline__ unsigned long long packkey(float s, int idx) {
    unsigned u = __float_as_uint(s);
    u = (u & 0x80000000u) ? ~u : (u | 0x80000000u);
    unsigned hi = ~u;
    return ((unsigned long long)hi << 32) | (unsigned)idx;
}

__device__ __forceinline__ void bitonic1024(unsigned long long& key,
                                            unsigned long long* sk, int t) {
    for (int ksz = 2; ksz <= 1024; ksz <<= 1) {
        for (int j = ksz >> 1; j >= 32; j >>= 1) {
            sk[t] = key;
            __syncthreads();
            unsigned long long o = sk[t ^ j];
            bool keepmin = (((t & j) == 0) == ((t & ksz) == 0));
            key = (keepmin == (o < key)) ? o : key;
            __syncthreads();
        }
        int jmax = ((ksz >> 1) < 16) ? (ksz >> 1) : 16;
        for (int j = jmax; j >= 1; j >>= 1) {
            unsigned long long o = __shfl_xor_sync(0xffffffffu, key, j);
            bool keepmin = (((t & j) == 0) == ((t & ksz) == 0));
            key = (keepmin == (o < key)) ? o : key;
        }
    }
}

#define RELU(v) ((v) > 0.f ? (v) : 0.f)

// packed fp32x2 FMA (sm_100+): two bit-exact fp32 FMAs per instruction
__device__ __forceinline__ unsigned long long pack2(float lo, float hi) {
    unsigned long long r;
    asm("mov.b64 %0, {%1, %2};" : "=l"(r) : "f"(lo), "f"(hi));
    return r;
}
__device__ __forceinline__ void unpack2(unsigned long long v, float& lo, float& hi) {
    asm("mov.b64 {%0, %1}, %2;" : "=f"(lo), "=f"(hi) : "l"(v));
}
__device__ __forceinline__ unsigned long long ffma2(unsigned long long a,
                                                    unsigned long long b,
                                                    unsigned long long c) {
    unsigned long long d;
    asm("fma.rn.f32x2 %0, %1, %2, %3;" : "=l"(d) : "l"(a), "l"(b), "l"(c));
    return d;
}

// ---------------- init --------------------------------------------------------

__global__ void k_zero_mask() {
    int i = blockIdx.x * blockDim.x + threadIdx.x;
    if (i < NTOT) g_mask1[i] = 0;
}

// ---------------- layer-1/2 LUT machinery --------------------------------------

__global__ void k_mask1(const int* __restrict__ src,
                        const int* __restrict__ dst,
                        const int* __restrict__ x_ids) {
    int e = blockIdx.x * blockDim.x + threadIdx.x;
    if (e >= ETOT) return;
    atomicOr(&g_mask1[dst[e]], 1 << x_ids[src[e]]);
}

// All LUTs in one 256-thread block (standalone: keeps its smem off other kernels).
__global__ void __launch_bounds__(256)
k_lut1(const float* __restrict__ emb,
       const float* __restrict__ W1, const float* __restrict__ b1,
       const float* __restrict__ U1, const float* __restrict__ p1,
       const float* __restrict__ W2, const float* __restrict__ b2,
       const float* __restrict__ U2) {
    __shared__ float s_emb[4][64], s_m1[4][64], s_amax[16][64];
    __shared__ float s_y1[32][64], s_x2[32][64];
    __shared__ float s_scale[32];
    __shared__ float s_pinv;
    int t = threadIdx.x;
    s_emb[t >> 6][t & 63] = emb[t];
    if (t == 0) {
        float s = 0.f;
        for (int i = 0; i < 64; i++) s += p1[i] * p1[i];
        s_pinv = 1.0f / sqrtf(s);
    }
    __syncthreads();
    {
        int id = t >> 6, o = t & 63;
        float a = b1[o];
        for (int i = 0; i < 64; i++) a = fmaf(s_emb[id][i], W1[o * 64 + i], a);
        s_m1[id][o] = RELU(a);
    }
    __syncthreads();
    for (int u = t; u < 16 * 64; u += 256) {
        int mask = u >> 6, o = u & 63;
        float v = NEG_INF;
        for (int id = 0; id < 4; id++)
            if ((mask >> id) & 1) v = fmaxf(v, s_m1[id][o]);
        if (mask == 0) v = 0.f;
        s_amax[mask][o] = v;
    }
    __syncthreads();
    for (int u = t; u < 32 * 64; u += 256) {
        int cc = u >> 6, o = u & 63;
        int id = cc >> 3, m3 = cc & 7;
        int lower = m3 & ((1 << id) - 1);
        int upper = (m3 >> id) << (id + 1);
        int mask = lower | upper | (1 << id);
        float a = 0.f;
        for (int i = 0; i < 64; i++) a = fmaf(s_amax[mask][i], U1[o * 128 + i], a);
        for (int i = 0; i < 64; i++) a = fmaf(s_emb[id][i], U1[o * 128 + 64 + i], a);
        s_y1[cc][o] = RELU(a);
    }
    __syncthreads();
    if (t < 32) {
        float s = 0.f;
        for (int i = 0; i < 64; i++) s = fmaf(s_y1[t][i], p1[i], s);
        s *= s_pinv;
        g_sc1lut[t] = s;
        s_scale[t]  = tanhf(s);
    }
    __syncthreads();
    for (int u = t; u < 32 * 64; u += 256) {
        int cc = u >> 6, d = u & 63;
        float v = s_y1[cc][d] * s_scale[cc];
        s_x2[cc][d] = v;
        g_x2lut[u] = v;
    }
    __syncthreads();
    for (int u = t; u < 32 * 64; u += 256) {
        int cc = u >> 6, o = u & 63;
        float a = b2[o];
        for (int i = 0; i < 64; i++) a = fmaf(s_x2[cc][i], W2[o * 64 + i], a);
        g_msg2lut[u] = RELU(a);
        float x = 0.f;
        for (int i = 0; i < 64; i++) x = fmaf(s_x2[cc][i], U2[o * 128 + 64 + i], x);
        g_x2part[u] = x;
    }
}

// ---------------- topk kernels --------------------------------------------------

__global__ void __launch_bounds__(1024)
k_topk1(const int* __restrict__ x_ids) {
    __shared__ unsigned long long sk[1024];
    __shared__ unsigned char scb[1024];
    int b = blockIdx.x, t = threadIdx.x;
    int node = b * 1024 + t;
    int id = x_ids[node];
    int mask = g_mask1[node] | (1 << id);
    int lower = mask & ((1 << id) - 1);
    int upper = (mask >> (id + 1)) << id;
    int cc = id * 8 + (lower | upper);
    scb[t] = (unsigned char)cc;
    unsigned long long key = packkey(g_sc1lut[cc], t);
    g_inv[node] = -1;
    __syncthreads();
    bitonic1024(key, sk, t);
    if (t < K1) {
        int idx = (int)(key & 0xffffffffu);
        int old = b * 1024 + idx;
        int nw  = b * K1 + t;
        g_inv[old]   = nw;
        int c = scb[idx];
        g_combo2[nw] = c;
        g_pres2[nw]  = 1u << c;
    }
}

__global__ void __launch_bounds__(1024)
k_topk(int n_per, int k, int write_inv) {
    __shared__ unsigned long long sk[1024];
    int b = blockIdx.x, t = threadIdx.x;
    unsigned long long key = 0xFFFFFFFFFFFFFFFFull;
    if (t < n_per) {
        key = packkey(g_score[b * n_per + t], t);
        if (write_inv) g_inv[b * n_per + t] = -1;
    }
    __syncthreads();
    bitonic1024(key, sk, t);
    if (t < k) {
        int idx = (int)(key & 0xffffffffu);
        int old = b * n_per + idx;
        int nw  = b * k + t;
        g_selold[nw]   = old;
        g_selscale[nw] = tanhf(g_score[old]);
        if (write_inv) g_inv[old] = nw;
    }
}

// ---------------- fused thin-kernel bodies (all smem-tiny) ------------------------

// raw edges -> bank 0 (ns=-1 sentinel); fused layer-2 presence OR
__device__ __forceinline__ void body_remap1(int e, const int* __restrict__ src,
                                            const int* __restrict__ dst) {
    if (e >= ETOT) return;
    int ns = g_inv[src[e]];
    int nd = g_inv[dst[e]];
    bool nm = (ns >= 0) && (nd >= 0);
    g_esrc[0][e] = nm ? ns : -1;
    g_edst[0][e] = nm ? nd : 0;
    if (nm) atomicOr(&g_pres2[nd], 1u << g_combo2[ns]);
}

// layer-1 readout via per-combo counting; FIRST writer of g_h (plain store)
__device__ __forceinline__ void body_readout1c(int b, int t) {
    __shared__ int cnt[32];
    if (t < 32) cnt[t] = 0;
    __syncthreads();
    for (int j = t; j < K1; j += 256)
        atomicAdd(&cnt[g_combo2[b * K1 + j]], 1);
    __syncthreads();
    if (t < 64) {
        float mx = NEG_INF, sm = 0.f;
        for (int c = 0; c < 32; c++) {
            int n = cnt[c];
            if (n > 0) {
                float v = g_x2lut[c * 64 + t];
                mx = fmaxf(mx, v);
                sm = fmaf((float)n, v, sm);
            }
        }
        g_h[b * 128 + t]      = mx;
        g_h[b * 128 + 64 + t] = sm / (float)K1;
    }
}

__device__ __forceinline__ void body_cmax(int i) {
    int d = i & 63;
    int v = (i >> 6) & 255;
    int ch = i >> 14;
    float m = NEG_INF;
#pragma unroll
    for (int b = 0; b < 8; b++)
        if ((v >> b) & 1) m = fmaxf(m, g_msg2lut[(ch * 8 + b) * 64 + d]);
    g_cmax[i] = m;
}

#define EB 8192   // ETOT/256

// t1 = remap1 (8192) + readout1c (128) + cmax (256) + zero_deg (512)
__global__ void __launch_bounds__(256)
k_t1(const int* __restrict__ src, const int* __restrict__ dst) {
    int blk = blockIdx.x, t = threadIdx.x;
    if (blk < EB) {
        body_remap1(blk * 256 + t, src, dst);
    } else if (blk < EB + BGR) {
        body_readout1c(blk - EB, t);
    } else if (blk < EB + BGR + 256) {
        body_cmax((blk - EB - BGR) * 256 + t);
    } else {
        int i = (blk - EB - BGR - 256) * 256 + t;
        if (i < NTOT) g_deg[i] = 0;
    }
}

// flat gather
__device__ __forceinline__ void body_gather(int idx, int nk) {
    if (idx >= nk * DD) return;
    int j = idx >> 6, d = idx & 63;
    g_x[idx] = g_y[(size_t)g_selold[j] * DD + d] * g_selscale[j];
}

// bank0 -> bank1, fused degree count
__device__ __forceinline__ void body_remap2(int e) {
    if (e >= ETOT) return;
    int s0 = g_esrc[0][e];
    int ns = -1, nd = 0;
    if (s0 >= 0) {
        ns = g_inv[s0];
        nd = g_inv[g_edst[0][e]];
        if (nd < 0) ns = -1;
        else if (ns >= 0) atomicAdd(&g_deg[nd], 1);
    }
    g_esrc[1][e] = ns;
    g_edst[1][e] = (ns >= 0) ? nd : 0;
}

#define GB2 20992   // (83968*64)/256

// t2 = gather(n3) + remap2
__global__ void __launch_bounds__(256)
k_t2(int nk) {
    int blk = blockIdx.x, t = threadIdx.x;
    if (blk < GB2) body_gather(blk * 256 + t, nk);
    else           body_remap2((blk - GB2) * 256 + t);
}

// contiguous readout over g_x (256 threads, 4 slices)
__device__ __forceinline__ void body_readout(int b, int t, int k) {
    __shared__ float smx[4][64], ssm[4][64];
    int d = t & 63, r = t >> 6;
    int per = (k + 3) / 4;
    int j0 = r * per;
    int j1 = min(k, j0 + per);
    float mx = NEG_INF, sm = 0.f;
    const float* base = g_x + (size_t)b * k * DD + d;
    for (int j = j0; j < j1; j++) {
        float v = base[(size_t)j * DD];
        mx = fmaxf(mx, v);
        sm += v;
    }
    smx[r][d] = mx; ssm[r][d] = sm;
    __syncthreads();
    if (r == 0) {
#pragma unroll
        for (int i = 1; i < 4; i++) {
            mx = fmaxf(mx, smx[i][d]);
            sm += ssm[i][d];
        }
        g_h[b * 128 + d]      += mx;
        g_h[b * 128 + 64 + d] += sm / (float)k;
    }
}

// 256-thread exclusive scan over n_per (<=1024, multiple of 4) degrees
__device__ __forceinline__ void body_scan256(int g, int t, int n_per) {
    __shared__ int wsum[8];
    int lane = t & 31, wid = t >> 5;
    int4 v = make_int4(0, 0, 0, 0);
    int base = g * n_per + t * 4;
    bool act = (t * 4 < n_per);
    if (act) v = *(const int4*)(g_deg + base);
    int s = v.x + v.y + v.z + v.w;
    int x = s;
#pragma unroll
    for (int off = 1; off < 32; off <<= 1) {
        int u = __shfl_up_sync(0xffffffffu, x, off);
        if (lane >= off) x += u;
    }
    if (lane == 31) wsum[wid] = x;
    __syncthreads();
    if (t == 0) {
        int a = 0;
#pragma unroll
        for (int i = 0; i < 8; i++) { int tmp = wsum[i]; wsum[i] = a; a += tmp; }
    }
    __syncthreads();
    if (act) {
        int h = g * EPG + wsum[wid] + (x - s);
        g_headp[base + 0] = h; g_cur[base + 0] = h; h += v.x;
        g_headp[base + 1] = h; g_cur[base + 1] = h; h += v.y;
        g_headp[base + 2] = h; g_cur[base + 2] = h; h += v.z;
        g_headp[base + 3] = h; g_cur[base + 3] = h;
    }
}

// t3 = readout(K2) (128 blocks) + scan256 (128 blocks)
__global__ void __launch_bounds__(256)
k_t3() {
    int blk = blockIdx.x, t = threadIdx.x;
    if (blk < BGR) body_readout(blk, t, K2);
    else           body_scan256(blk - BGR, t, K2);
}

__global__ void k_fill() {
    int e = blockIdx.x * blockDim.x + threadIdx.x;
    if (e >= ETOT) return;
    int s = g_esrc[1][e];
    if (s < 0) return;
    int d = g_edst[1][e];
    int pos = atomicAdd(&g_cur[d], 1);
    g_csr[pos] = s;
}

// standalone gather/readout for layer-3 tail
__global__ void k_gather(int nk) {
    body_gather(blockIdx.x * blockDim.x + threadIdx.x, nk);
}
__global__ void __launch_bounds__(256)
k_readout(int k) {
    body_readout(blockIdx.x, threadIdx.x, k);
}

// ---------------- aggregation ---------------------------------------------------

__global__ void k_aggr2(int n) {
    int w = (blockIdx.x * blockDim.x + threadIdx.x) >> 5;
    int lane = threadIdx.x & 31;
    if (w >= n) return;
    unsigned m = g_pres2[w];
    float m0 = NEG_INF, m1 = NEG_INF;
#pragma unroll
    for (int ch = 0; ch < 4; ch++) {
        unsigned v = (m >> (ch * 8)) & 255u;
        if (v) {
            const float* r = g_cmax + ((ch << 8) | v) * 64;
            m0 = fmaxf(m0, __ldg(r + lane));
            m1 = fmaxf(m1, __ldg(r + lane + 32));
        }
    }
    float* ar = g_aggr + (size_t)w * DD;
    ar[lane]      = m0;
    ar[lane + 32] = m1;
}

__global__ void k_aggr3(int n) {
    int w = (blockIdx.x * blockDim.x + threadIdx.x) >> 5;
    int lane = threadIdx.x & 31;
    if (w >= n) return;
    const float* mrow = g_msg + (size_t)w * DD;
    float m0 = mrow[lane];
    float m1 = mrow[lane + 32];
    int e   = g_headp[w];
    int end = g_cur[w];
    for (; e + 4 <= end; e += 4) {
        int s0 = __ldg(&g_csr[e]);
        int s1 = __ldg(&g_csr[e + 1]);
        int s2 = __ldg(&g_csr[e + 2]);
        int s3 = __ldg(&g_csr[e + 3]);
        const float* r0 = g_msg + (size_t)s0 * DD;
        const float* r1 = g_msg + (size_t)s1 * DD;
        const float* r2 = g_msg + (size_t)s2 * DD;
        const float* r3 = g_msg + (size_t)s3 * DD;
        float a0 = r0[lane], b0 = r0[lane + 32];
        float a1 = r1[lane], b1 = r1[lane + 32];
        float a2 = r2[lane], b2 = r2[lane + 32];
        float a3 = r3[lane], b3 = r3[lane + 32];
        m0 = fmaxf(fmaxf(fmaxf(m0, a0), fmaxf(a1, a2)), a3);
        m1 = fmaxf(fmaxf(fmaxf(m1, b0), fmaxf(b1, b2)), b3);
    }
    for (; e < end; e++) {
        int s0 = __ldg(&g_csr[e]);
        const float* r0 = g_msg + (size_t)s0 * DD;
        m0 = fmaxf(m0, r0[lane]);
        m1 = fmaxf(m1, r0[lane + 32]);
    }
    float* ar = g_aggr + (size_t)w * DD;
    ar[lane]      = m0;
    ar[lane + 32] = m1;
}

// ---------------- GEMMs (f32x2 packed FMA + float4 row I/O, R10 form) --------------

__global__ void __launch_bounds__(128)
k_gemm64(const float* __restrict__ W, const float* __restrict__ bias, int n) {
    __shared__ float Wt[64][64];
    for (int t = threadIdx.x; t < 64 * 64; t += blockDim.x) {
        int o = t >> 6, i = t & 63;
        Wt[i][o] = W[t];
    }
    __syncthreads();
    int row = blockIdx.x * blockDim.x + threadIdx.x;
    if (row >= n) return;
    const float4* xr4 = (const float4*)(g_x + (size_t)row * DD);
    unsigned long long acc[32];
#pragma unroll
    for (int o = 0; o < 32; o++) acc[o] = pack2(bias[2 * o], bias[2 * o + 1]);
#pragma unroll
    for (int c = 0; c < 4; c++) {
        float4 v0 = xr4[c * 4 + 0], v1 = xr4[c * 4 + 1];
        float4 v2 = xr4[c * 4 + 2], v3 = xr4[c * 4 + 3];
        float xv[16] = {v0.x, v0.y, v0.z, v0.w, v1.x, v1.y, v1.z, v1.w,
                        v2.x, v2.y, v2.z, v2.w, v3.x, v3.y, v3.z, v3.w};
#pragma unroll
        for (int ii = 0; ii < 16; ii++) {
            int i = c * 16 + ii;
            unsigned long long xv2 = pack2(xv[ii], xv[ii]);
            const unsigned long long* wt2 = (const unsigned long long*)&Wt[i][0];
#pragma unroll
            for (int o = 0; o < 32; o++) acc[o] = ffma2(xv2, wt2[o], acc[o]);
        }
    }
    float4* mr4 = (float4*)(g_msg + (size_t)row * DD);
#pragma unroll
    for (int c = 0; c < 16; c++) {
        float a0, a1, a2, a3;
        unpack2(acc[c * 2 + 0], a0, a1);
        unpack2(acc[c * 2 + 1], a2, a3);
        float4 w;
        w.x = RELU(a0); w.y = RELU(a1); w.z = RELU(a2); w.w = RELU(a3);
        mr4[c] = w;
    }
}

// layer-2: y = relu(aggr @ Ua^T + x2part[combo]); fused score
__global__ void __launch_bounds__(128)
k_gemmcat2(const float* __restrict__ U, const float* __restrict__ p, int n) {
    __shared__ float Ut[64][64];
    __shared__ float x2p[32][64];
    __shared__ float ps[64];
    __shared__ float pinv;
    for (int t = threadIdx.x; t < 64 * 64; t += blockDim.x) {
        int o = t >> 6, i = t & 63;
        Ut[i][o] = U[o * 128 + i];
    }
    for (int t = threadIdx.x; t < 32 * 64; t += blockDim.x)
        x2p[t >> 6][t & 63] = g_x2part[t];
    if (threadIdx.x < 64) ps[threadIdx.x] = p[threadIdx.x];
    __syncthreads();
    if (threadIdx.x == 0) {
        float s = 0.f;
        for (int i = 0; i < 64; i++) s += ps[i] * ps[i];
        pinv = 1.0f / sqrtf(s);
    }
    __syncthreads();
    int row = blockIdx.x * blockDim.x + threadIdx.x;
    if (row >= n) return;
    int cmb = g_combo2[row];
    const float4* ar4 = (const float4*)(g_aggr + (size_t)row * DD);
    const unsigned long long* xp2 = (const unsigned long long*)&x2p[cmb][0];
    unsigned long long acc[32];
#pragma unroll
    for (int o = 0; o < 32; o++) acc[o] = xp2[o];
#pragma unroll
    for (int c = 0; c < 4; c++) {
        float4 v0 = ar4[c * 4 + 0], v1 = ar4[c * 4 + 1];
        float4 v2 = ar4[c * 4 + 2], v3 = ar4[c * 4 + 3];
        float av[16] = {v0.x, v0.y, v0.z, v0.w, v1.x, v1.y, v1.z, v1.w,
                        v2.x, v2.y, v2.z, v2.w, v3.x, v3.y, v3.z, v3.w};
#pragma unroll
        for (int ii = 0; ii < 16; ii++) {
            int i = c * 16 + ii;
            unsigned long long av2 = pack2(av[ii], av[ii]);
            const unsigned long long* ut2 = (const unsigned long long*)&Ut[i][0];
#pragma unroll
            for (int o = 0; o < 32; o++) acc[o] = ffma2(av2, ut2[o], acc[o]);
        }
    }
    float4* yr4 = (float4*)(g_y + (size_t)row * DD);
    float sc = 0.f;
#pragma unroll
    for (int c = 0; c < 16; c++) {
        float a0, a1, a2, a3;
        unpack2(acc[c * 2 + 0], a0, a1);
        unpack2(acc[c * 2 + 1], a2, a3);
        float4 w;
        w.x = RELU(a0); w.y = RELU(a1); w.z = RELU(a2); w.w = RELU(a3);
        yr4[c] = w;
        sc = fmaf(w.x, ps[c * 4 + 0], sc);
        sc = fmaf(w.y, ps[c * 4 + 1], sc);
        sc = fmaf(w.z, ps[c * 4 + 2], sc);
        sc = fmaf(w.w, ps[c * 4 + 3], sc);
    }
    g_score[row] = sc * pinv;
}

// layer-3 full concat GEMM + fused score
__global__ void __launch_bounds__(128)
k_gemmcat(const float* __restrict__ U, const float* __restrict__ p, int n) {
    __shared__ float Ut[128][64];
    __shared__ float ps[64];
    __shared__ float pinv;
    for (int t = threadIdx.x; t < 128 * 64; t += blockDim.x) {
        int o = t >> 7, i = t & 127;
        Ut[i][o] = U[t];
    }
    if (threadIdx.x < 64) ps[threadIdx.x] = p[threadIdx.x];
    __syncthreads();
    if (threadIdx.x == 0) {
        float s = 0.f;
        for (int i = 0; i < 64; i++) s += ps[i] * ps[i];
        pinv = 1.0f / sqrtf(s);
    }
    __syncthreads();
    int row = blockIdx.x * blockDim.x + threadIdx.x;
    if (row >= n) return;
    const float4* ar4 = (const float4*)(g_aggr + (size_t)row * DD);
    const float4* xr4 = (const float4*)(g_x   + (size_t)row * DD);
    unsigned long long acc[32];
#pragma unroll
    for (int o = 0; o < 32; o++) acc[o] = 0ull;
#pragma unroll
    for (int c = 0; c < 4; c++) {
        float4 v0 = ar4[c * 4 + 0], v1 = ar4[c * 4 + 1];
        float4 v2 = ar4[c * 4 + 2], v3 = ar4[c * 4 + 3];
        float av[16] = {v0.x, v0.y, v0.z, v0.w, v1.x, v1.y, v1.z, v1.w,
                        v2.x, v2.y, v2.z, v2.w, v3.x, v3.y, v3.z, v3.w};
#pragma unroll
        for (int ii = 0; ii < 16; ii++) {
            int i = c * 16 + ii;
            unsigned long long av2 = pack2(av[ii], av[ii]);
            const unsigned long long* ut2 = (const unsigned long long*)&Ut[i][0];
#pragma unroll
            for (int o = 0; o < 32; o++) acc[o] = ffma2(av2, ut2[o], acc[o]);
        }
    }
#pragma unroll
    for (int c = 0; c < 4; c++) {
        float4 v0 = xr4[c * 4 + 0], v1 = xr4[c * 4 + 1];
        float4 v2 = xr4[c * 4 + 2], v3 = xr4[c * 4 + 3];
        float xv[16] = {v0.x, v0.y, v0.z, v0.w, v1.x, v1.y, v1.z, v1.w,
                        v2.x, v2.y, v2.z, v2.w, v3.x, v3.y, v3.z, v3.w};
#pragma unroll
        for (int ii = 0; ii < 16; ii++) {
            int i = 64 + c * 16 + ii;
            unsigned long long xv2 = pack2(xv[ii], xv[ii]);
            const unsigned long long* ut2 = (const unsigned long long*)&Ut[i][0];
#pragma unroll
            for (int o = 0; o < 32; o++) acc[o] = ffma2(xv2, ut2[o], acc[o]);
        }
    }
    float4* yr4 = (float4*)(g_y + (size_t)row * DD);
    float sc = 0.f;
#pragma unroll
    for (int c = 0; c < 16; c++) {
        float a0, a1, a2, a3;
        unpack2(acc[c * 2 + 0], a0, a1);
        unpack2(acc[c * 2 + 1], a2, a3);
        float4 w;
        w.x = RELU(a0); w.y = RELU(a1); w.z = RELU(a2); w.w = RELU(a3);
        yr4[c] = w;
        sc = fmaf(w.x, ps[c * 4 + 0], sc);
        sc = fmaf(w.y, ps[c * 4 + 1], sc);
        sc = fmaf(w.z, ps[c * 4 + 2], sc);
        sc = fmaf(w.w, ps[c * 4 + 3], sc);
    }
    g_score[row] = sc * pinv;
}

// ---------------- head ------------------------------------------------------------

__global__ void k_mlp(const float* __restrict__ l1W, const float* __restrict__ l1b,
                      const float* __restrict__ l2W, const float* __restrict__ l2b,
                      const float* __restrict__ l3W, const float* __restrict__ l3b,
                      float* __restrict__ out, int out_size) {
    int b = blockIdx.x;
    int o = threadIdx.x;   // 64
    __shared__ float h[128], s1[64], s2[64];
    h[o]      = g_h[b * 128 + o];
    h[o + 64] = g_h[b * 128 + 64 + o];
    __syncthreads();
    float a = l1b[o];
#pragma unroll 8
    for (int i = 0; i < 128; i++) a = fmaf(h[i], l1W[o * 128 + i], a);
    s1[o] = fmaxf(a, 0.f);
    __syncthreads();
    a = l2b[o];
#pragma unroll 8
    for (int i = 0; i < 64; i++) a = fmaf(s1[i], l2W[o * 64 + i], a);
    s2[o] = fmaxf(a, 0.f);
    __syncthreads();
    a = l3b[o];
#pragma unroll 8
    for (int i = 0; i < 64; i++) a = fmaf(s2[i], l3W[o * 64 + i], a);
    out[b * 64 + o] = 1.f / (1.f + expf(-a));
    for (int i = o; i < K3; i += 64) {
        int pos = 8192 + b * K3 + i;
        if (pos < out_size) out[pos] = (float)b;
    }
}

// ---------------- host orchestration ----------------------------------------------

extern "C" void kernel_launch(void* const* d_in, const int* in_sizes, int n_in,
                              void* d_out, int out_size) {
    const int*   x_ids = (const int*)d_in[0];
    const int*   eidx  = (const int*)d_in[1];
    const float* emb   = (const float*)d_in[2];
    const float* W1 = (const float*)d_in[3];
    const float* b1 = (const float*)d_in[4];
    const float* U1 = (const float*)d_in[5];
    const float* p1 = (const float*)d_in[6];
    const float* W2 = (const float*)d_in[7];
    const float* b2 = (const float*)d_in[8];
    const float* U2 = (const float*)d_in[9];
    const float* p2 = (const float*)d_in[10];
    const float* W3 = (const float*)d_in[11];
    const float* b3 = (const float*)d_in[12];
    const float* U3 = (const float*)d_in[13];
    const float* p3 = (const float*)d_in[14];
    const float* l1W = (const float*)d_in[15];
    const float* l1b = (const float*)d_in[16];
    const float* l2W = (const float*)d_in[17];
    const float* l2b = (const float*)d_in[18];
    const float* l3W = (const float*)d_in[19];
    const float* l3b = (const float*)d_in[20];
    float* out = (float*)d_out;

    const int eb = ETOT / 256;
    const int n2 = BGR * K1;   // 104960
    const int n3 = BGR * K2;   // 83968

    // ---- layer 1 ----
    k_zero_mask<<<(NTOT + 255) / 256, 256>>>();
    k_mask1<<<eb, 256>>>(eidx, eidx + ETOT, x_ids);
    k_lut1<<<1, 256>>>(emb, W1, b1, U1, p1, W2, b2, U2);
    k_topk1<<<BGR, 1024>>>(x_ids);
    k_t1<<<EB + BGR + 256 + 512, 256>>>(eidx, eidx + ETOT);

    // ---- layer 2 ----
    k_aggr2<<<(n2 * 32 + 255) / 256, 256>>>(n2);
    k_gemmcat2<<<(n2 + 127) / 128, 128>>>(U2, p2, n2);
    k_topk<<<BGR, 1024>>>(K1, K2, 1);
    k_t2<<<GB2 + EB, 256>>>(n3);                 // gather(n3) + remap2
    k_t3<<<BGR * 2, 256>>>();                    // readout(K2) + scan256
    k_fill<<<eb, 256>>>();

    // ---- layer 3 ----
    k_gemm64<<<(n3 + 127) / 128, 128>>>(W3, b3, n3);
    k_aggr3<<<(n3 * 32 + 255) / 256, 256>>>(n3);
    k_gemmcat<<<(n3 + 127) / 128, 128>>>(U3, p3, n3);
    k_topk<<<BGR, 1024>>>(K2, K3, 0);
    int nk3 = BGR * K3;
    k_gather<<<(nk3 * DD + 255) / 256, 256>>>(nk3);
    k_readout<<<BGR, 256>>>(K3);

    // ---- head ----
    k_mlp<<<BGR, 64>>>(l1W, l1b, l2W, l2b, l3W, l3b, out, out_size);
}

// round 13
// speedup vs baseline: 1.1312x; 1.0087x over previous
#include <cuda_runtime.h>
#include <math.h>

// Problem constants
#define BGR   128
#define N0    1024
#define NTOT  131072
#define ETOT  2097152
#define EPG   16384
#define DD    64
#define K1    820
#define K2    656
#define K3    525

#define NEG_INF __int_as_float(0xff800000)

// ---------------- scratch ---------------------------------------------------
__device__ float g_x[NTOT * DD];
__device__ float g_y[NTOT * DD];
__device__ float g_msg[NTOT * DD];
__device__ float g_aggr[NTOT * DD];
__device__ float g_score[NTOT];
__device__ int   g_selold[NTOT];
__device__ float g_selscale[NTOT];
__device__ int   g_inv[NTOT];
__device__ int   g_esrc[2][ETOT];     // -1 sentinel = invalid edge
__device__ int   g_edst[2][ETOT];
__device__ float g_h[BGR * 2 * DD];
// CSR scratch (layer 3)
__device__ int   g_deg[NTOT];
__device__ int   g_headp[NTOT];
__device__ int   g_cur[NTOT];
__device__ int   g_csr[ETOT];
// combo / LUT scratch; combos compressed to 0..31
__device__ int      g_mask1[NTOT];
__device__ int      g_combo2[NTOT];
__device__ unsigned g_pres2[NTOT];
__device__ float g_sc1lut[32];
__device__ float g_x2lut[32 * 64];
__device__ float g_msg2lut[32 * 64];
__device__ float g_x2part[32 * 64];
__device__ float g_cmax[4 * 256 * 64];

// ---------------- helpers ----------------------------------------------------

__device__ __forceinline__ unsigned long long packkey(float s, int idx) {
    unsigned u = __float_as_uint(s);
    u = (u & 0x80000000u) ? ~u : (u | 0x80000000u);
    unsigned hi = ~u;
    return ((unsigned long long)hi << 32) | (unsigned)idx;
}

__device__ __forceinline__ void bitonic1024(unsigned long long& key,
                                            unsigned long long* sk, int t) {
    for (int ksz = 2; ksz <= 1024; ksz <<= 1) {
        for (int j = ksz >> 1; j >= 32; j >>= 1) {
            sk[t] = key;
            __syncthreads();
            unsigned long long o = sk[t ^ j];
            bool keepmin = (((t & j) == 0) == ((t & ksz) == 0));
            key = (keepmin == (o < key)) ? o : key;
            __syncthreads();
        }
        int jmax = ((ksz >> 1) < 16) ? (ksz >> 1) : 16;
        for (int j = jmax; j >= 1; j >>= 1) {
            unsigned long long o = __shfl_xor_sync(0xffffffffu, key, j);
            bool keepmin = (((t & j) == 0) == ((t & ksz) == 0));
            key = (keepmin == (o < key)) ? o : key;
        }
    }
}

#define RELU(v) ((v) > 0.f ? (v) : 0.f)

// packed fp32x2 FMA (sm_100+): two bit-exact fp32 FMAs per instruction
__device__ __forceinline__ unsigned long long pack2(float lo, float hi) {
    unsigned long long r;
    asm("mov.b64 %0, {%1, %2};" : "=l"(r) : "f"(lo), "f"(hi));
    return r;
}
__device__ __forceinline__ void unpack2(unsigned long long v, float& lo, float& hi) {
    asm("mov.b64 {%0, %1}, %2;" : "=f"(lo), "=f"(hi) : "l"(v));
}
__device__ __forceinline__ unsigned long long ffma2(unsigned long long a,
                                                    unsigned long long b,
                                                    unsigned long long c) {
    unsigned long long d;
    asm("fma.rn.f32x2 %0, %1, %2, %3;" : "=l"(d) : "l"(a), "l"(b), "l"(c));
    return d;
}

// ---------------- init --------------------------------------------------------

__global__ void k_zero_mask() {
    int i = blockIdx.x * blockDim.x + threadIdx.x;
    if (i < NTOT) g_mask1[i] = 0;
}

// ---------------- layer-1/2 LUT machinery --------------------------------------

__global__ void k_mask1(const int* __restrict__ src,
                        const int* __restrict__ dst,
                        const int* __restrict__ x_ids) {
    int e = blockIdx.x * blockDim.x + threadIdx.x;
    if (e >= ETOT) return;
    atomicOr(&g_mask1[dst[e]], 1 << x_ids[src[e]]);
}

// All LUTs in one 256-thread block (standalone: keeps its smem off other kernels).
__global__ void __launch_bounds__(256)
k_lut1(const float* __restrict__ emb,
       const float* __restrict__ W1, const float* __restrict__ b1,
       const float* __restrict__ U1, const float* __restrict__ p1,
       const float* __restrict__ W2, const float* __restrict__ b2,
       const float* __restrict__ U2) {
    __shared__ float s_emb[4][64], s_m1[4][64], s_amax[16][64];
    __shared__ float s_y1[32][64], s_x2[32][64];
    __shared__ float s_scale[32];
    __shared__ float s_pinv;
    int t = threadIdx.x;
    s_emb[t >> 6][t & 63] = emb[t];
    if (t == 0) {
        float s = 0.f;
        for (int i = 0; i < 64; i++) s += p1[i] * p1[i];
        s_pinv = 1.0f / sqrtf(s);
    }
    __syncthreads();
    {
        int id = t >> 6, o = t & 63;
        float a = b1[o];
        for (int i = 0; i < 64; i++) a = fmaf(s_emb[id][i], W1[o * 64 + i], a);
        s_m1[id][o] = RELU(a);
    }
    __syncthreads();
    for (int u = t; u < 16 * 64; u += 256) {
        int mask = u >> 6, o = u & 63;
        float v = NEG_INF;
        for (int id = 0; id < 4; id++)
            if ((mask >> id) & 1) v = fmaxf(v, s_m1[id][o]);
        if (mask == 0) v = 0.f;
        s_amax[mask][o] = v;
    }
    __syncthreads();
    for (int u = t; u < 32 * 64; u += 256) {
        int cc = u >> 6, o = u & 63;
        int id = cc >> 3, m3 = cc & 7;
        int lower = m3 & ((1 << id) - 1);
        int upper = (m3 >> id) << (id + 1);
        int mask = lower | upper | (1 << id);
        float a = 0.f;
        for (int i = 0; i < 64; i++) a = fmaf(s_amax[mask][i], U1[o * 128 + i], a);
        for (int i = 0; i < 64; i++) a = fmaf(s_emb[id][i], U1[o * 128 + 64 + i], a);
        s_y1[cc][o] = RELU(a);
    }
    __syncthreads();
    if (t < 32) {
        float s = 0.f;
        for (int i = 0; i < 64; i++) s = fmaf(s_y1[t][i], p1[i], s);
        s *= s_pinv;
        g_sc1lut[t] = s;
        s_scale[t]  = tanhf(s);
    }
    __syncthreads();
    for (int u = t; u < 32 * 64; u += 256) {
        int cc = u >> 6, d = u & 63;
        float v = s_y1[cc][d] * s_scale[cc];
        s_x2[cc][d] = v;
        g_x2lut[u] = v;
    }
    __syncthreads();
    for (int u = t; u < 32 * 64; u += 256) {
        int cc = u >> 6, o = u & 63;
        float a = b2[o];
        for (int i = 0; i < 64; i++) a = fmaf(s_x2[cc][i], W2[o * 64 + i], a);
        g_msg2lut[u] = RELU(a);
        float x = 0.f;
        for (int i = 0; i < 64; i++) x = fmaf(s_x2[cc][i], U2[o * 128 + 64 + i], x);
        g_x2part[u] = x;
    }
}

// ---------------- topk kernels --------------------------------------------------

__global__ void __launch_bounds__(1024)
k_topk1(const int* __restrict__ x_ids) {
    __shared__ unsigned long long sk[1024];
    __shared__ unsigned char scb[1024];
    int b = blockIdx.x, t = threadIdx.x;
    int node = b * 1024 + t;
    int id = x_ids[node];
    int mask = g_mask1[node] | (1 << id);
    int lower = mask & ((1 << id) - 1);
    int upper = (mask >> (id + 1)) << id;
    int cc = id * 8 + (lower | upper);
    scb[t] = (unsigned char)cc;
    unsigned long long key = packkey(g_sc1lut[cc], t);
    g_inv[node] = -1;
    __syncthreads();
    bitonic1024(key, sk, t);
    if (t < K1) {
        int idx = (int)(key & 0xffffffffu);
        int old = b * 1024 + idx;
        int nw  = b * K1 + t;
        g_inv[old]   = nw;
        int c = scb[idx];
        g_combo2[nw] = c;
        g_pres2[nw]  = 1u << c;
    }
}

__global__ void __launch_bounds__(1024)
k_topk(int n_per, int k, int write_inv) {
    __shared__ unsigned long long sk[1024];
    int b = blockIdx.x, t = threadIdx.x;
    unsigned long long key = 0xFFFFFFFFFFFFFFFFull;
    if (t < n_per) {
        key = packkey(g_score[b * n_per + t], t);
        if (write_inv) g_inv[b * n_per + t] = -1;
    }
    __syncthreads();
    bitonic1024(key, sk, t);
    if (t < k) {
        int idx = (int)(key & 0xffffffffu);
        int old = b * n_per + idx;
        int nw  = b * k + t;
        g_selold[nw]   = old;
        g_selscale[nw] = tanhf(g_score[old]);
        if (write_inv) g_inv[old] = nw;
    }
}

// ---------------- fused thin-kernel bodies (all smem-tiny) ------------------------

// raw edges -> bank 0 (ns=-1 sentinel); fused layer-2 presence OR
__device__ __forceinline__ void body_remap1(int e, const int* __restrict__ src,
                                            const int* __restrict__ dst) {
    if (e >= ETOT) return;
    int ns = g_inv[src[e]];
    int nd = g_inv[dst[e]];
    bool nm = (ns >= 0) && (nd >= 0);
    g_esrc[0][e] = nm ? ns : -1;
    g_edst[0][e] = nm ? nd : 0;
    if (nm) atomicOr(&g_pres2[nd], 1u << g_combo2[ns]);
}

// layer-1 readout via per-combo counting; FIRST writer of g_h (plain store)
__device__ __forceinline__ void body_readout1c(int b, int t) {
    __shared__ int cnt[32];
    if (t < 32) cnt[t] = 0;
    __syncthreads();
    for (int j = t; j < K1; j += 256)
        atomicAdd(&cnt[g_combo2[b * K1 + j]], 1);
    __syncthreads();
    if (t < 64) {
        float mx = NEG_INF, sm = 0.f;
        for (int c = 0; c < 32; c++) {
            int n = cnt[c];
            if (n > 0) {
                float v = g_x2lut[c * 64 + t];
                mx = fmaxf(mx, v);
                sm = fmaf((float)n, v, sm);
            }
        }
        g_h[b * 128 + t]      = mx;
        g_h[b * 128 + 64 + t] = sm / (float)K1;
    }
}

__device__ __forceinline__ void body_cmax(int i) {
    int d = i & 63;
    int v = (i >> 6) & 255;
    int ch = i >> 14;
    float m = NEG_INF;
#pragma unroll
    for (int b = 0; b < 8; b++)
        if ((v >> b) & 1) m = fmaxf(m, g_msg2lut[(ch * 8 + b) * 64 + d]);
    g_cmax[i] = m;
}

#define EB 8192   // ETOT/256

// t1 = remap1 (8192) + readout1c (128) + cmax (256) + zero_deg (512)
__global__ void __launch_bounds__(256)
k_t1(const int* __restrict__ src, const int* __restrict__ dst) {
    int blk = blockIdx.x, t = threadIdx.x;
    if (blk < EB) {
        body_remap1(blk * 256 + t, src, dst);
    } else if (blk < EB + BGR) {
        body_readout1c(blk - EB, t);
    } else if (blk < EB + BGR + 256) {
        body_cmax((blk - EB - BGR) * 256 + t);
    } else {
        int i = (blk - EB - BGR - 256) * 256 + t;
        if (i < NTOT) g_deg[i] = 0;
    }
}

// flat gather
__device__ __forceinline__ void body_gather(int idx, int nk) {
    if (idx >= nk * DD) return;
    int j = idx >> 6, d = idx & 63;
    g_x[idx] = g_y[(size_t)g_selold[j] * DD + d] * g_selscale[j];
}

// bank0 -> bank1, fused degree count
__device__ __forceinline__ void body_remap2(int e) {
    if (e >= ETOT) return;
    int s0 = g_esrc[0][e];
    int ns = -1, nd = 0;
    if (s0 >= 0) {
        ns = g_inv[s0];
        nd = g_inv[g_edst[0][e]];
        if (nd < 0) ns = -1;
        else if (ns >= 0) atomicAdd(&g_deg[nd], 1);
    }
    g_esrc[1][e] = ns;
    g_edst[1][e] = (ns >= 0) ? nd : 0;
}

#define GB2 20992   // (83968*64)/256

// t2 = gather(n3) + remap2
__global__ void __launch_bounds__(256)
k_t2(int nk) {
    int blk = blockIdx.x, t = threadIdx.x;
    if (blk < GB2) body_gather(blk * 256 + t, nk);
    else           body_remap2((blk - GB2) * 256 + t);
}

// contiguous readout over g_x (256 threads, 4 slices)
__device__ __forceinline__ void body_readout(int b, int t, int k) {
    __shared__ float smx[4][64], ssm[4][64];
    int d = t & 63, r = t >> 6;
    int per = (k + 3) / 4;
    int j0 = r * per;
    int j1 = min(k, j0 + per);
    float mx = NEG_INF, sm = 0.f;
    const float* base = g_x + (size_t)b * k * DD + d;
    for (int j = j0; j < j1; j++) {
        float v = base[(size_t)j * DD];
        mx = fmaxf(mx, v);
        sm += v;
    }
    smx[r][d] = mx; ssm[r][d] = sm;
    __syncthreads();
    if (r == 0) {
#pragma unroll
        for (int i = 1; i < 4; i++) {
            mx = fmaxf(mx, smx[i][d]);
            sm += ssm[i][d];
        }
        g_h[b * 128 + d]      += mx;
        g_h[b * 128 + 64 + d] += sm / (float)k;
    }
}

// 256-thread exclusive scan over n_per (<=1024, multiple of 4) degrees
__device__ __forceinline__ void body_scan256(int g, int t, int n_per) {
    __shared__ int wsum[8];
    int lane = t & 31, wid = t >> 5;
    int4 v = make_int4(0, 0, 0, 0);
    int base = g * n_per + t * 4;
    bool act = (t * 4 < n_per);
    if (act) v = *(const int4*)(g_deg + base);
    int s = v.x + v.y + v.z + v.w;
    int x = s;
#pragma unroll
    for (int off = 1; off < 32; off <<= 1) {
        int u = __shfl_up_sync(0xffffffffu, x, off);
        if (lane >= off) x += u;
    }
    if (lane == 31) wsum[wid] = x;
    __syncthreads();
    if (t == 0) {
        int a = 0;
#pragma unroll
        for (int i = 0; i < 8; i++) { int tmp = wsum[i]; wsum[i] = a; a += tmp; }
    }
    __syncthreads();
    if (act) {
        int h = g * EPG + wsum[wid] + (x - s);
        g_headp[base + 0] = h; g_cur[base + 0] = h; h += v.x;
        g_headp[base + 1] = h; g_cur[base + 1] = h; h += v.y;
        g_headp[base + 2] = h; g_cur[base + 2] = h; h += v.z;
        g_headp[base + 3] = h; g_cur[base + 3] = h;
    }
}

// t3 = readout(K2) (128 blocks) + scan256 (128 blocks)
__global__ void __launch_bounds__(256)
k_t3() {
    int blk = blockIdx.x, t = threadIdx.x;
    if (blk < BGR) body_readout(blk, t, K2);
    else           body_scan256(blk - BGR, t, K2);
}

__global__ void k_fill() {
    int e = blockIdx.x * blockDim.x + threadIdx.x;
    if (e >= ETOT) return;
    int s = g_esrc[1][e];
    if (s < 0) return;
    int d = g_edst[1][e];
    int pos = atomicAdd(&g_cur[d], 1);
    g_csr[pos] = s;
}

// standalone gather/readout for layer-3 tail
__global__ void k_gather(int nk) {
    body_gather(blockIdx.x * blockDim.x + threadIdx.x, nk);
}
__global__ void __launch_bounds__(256)
k_readout(int k) {
    body_readout(blockIdx.x, threadIdx.x, k);
}

// ---------------- aggregation ---------------------------------------------------

__global__ void k_aggr2(int n) {
    int w = (blockIdx.x * blockDim.x + threadIdx.x) >> 5;
    int lane = threadIdx.x & 31;
    if (w >= n) return;
    unsigned m = g_pres2[w];
    float m0 = NEG_INF, m1 = NEG_INF;
#pragma unroll
    for (int ch = 0; ch < 4; ch++) {
        unsigned v = (m >> (ch * 8)) & 255u;
        if (v) {
            const float* r = g_cmax + ((ch << 8) | v) * 64;
            m0 = fmaxf(m0, __ldg(r + lane));
            m1 = fmaxf(m1, __ldg(r + lane + 32));
        }
    }
    float* ar = g_aggr + (size_t)w * DD;
    ar[lane]      = m0;
    ar[lane + 32] = m1;
}

__global__ void k_aggr3(int n) {
    int w = (blockIdx.x * blockDim.x + threadIdx.x) >> 5;
    int lane = threadIdx.x & 31;
    if (w >= n) return;
    const float* mrow = g_msg + (size_t)w * DD;
    float m0 = mrow[lane];
    float m1 = mrow[lane + 32];
    int e   = g_headp[w];
    int end = g_cur[w];
    for (; e + 4 <= end; e += 4) {
        int s0 = __ldg(&g_csr[e]);
        int s1 = __ldg(&g_csr[e + 1]);
        int s2 = __ldg(&g_csr[e + 2]);
        int s3 = __ldg(&g_csr[e + 3]);
        const float* r0 = g_msg + (size_t)s0 * DD;
        const float* r1 = g_msg + (size_t)s1 * DD;
        const float* r2 = g_msg + (size_t)s2 * DD;
        const float* r3 = g_msg + (size_t)s3 * DD;
        float a0 = r0[lane], b0 = r0[lane + 32];
        float a1 = r1[lane], b1 = r1[lane + 32];
        float a2 = r2[lane], b2 = r2[lane + 32];
        float a3 = r3[lane], b3 = r3[lane + 32];
        m0 = fmaxf(fmaxf(fmaxf(m0, a0), fmaxf(a1, a2)), a3);
        m1 = fmaxf(fmaxf(fmaxf(m1, b0), fmaxf(b1, b2)), b3);
    }
    for (; e < end; e++) {
        int s0 = __ldg(&g_csr[e]);
        const float* r0 = g_msg + (size_t)s0 * DD;
        m0 = fmaxf(m0, r0[lane]);
        m1 = fmaxf(m1, r0[lane + 32]);
    }
    float* ar = g_aggr + (size_t)w * DD;
    ar[lane]      = m0;
    ar[lane + 32] = m1;
}

// ---------------- GEMMs (f32x2 FMA + LDS.128 weight loads + float4 row I/O) --------

__global__ void __launch_bounds__(128)
k_gemm64(const float* __restrict__ W, const float* __restrict__ bias, int n) {
    __shared__ __align__(16) float Wt[64][64];
    for (int t = threadIdx.x; t < 64 * 64; t += blockDim.x) {
        int o = t >> 6, i = t & 63;
        Wt[i][o] = W[t];
    }
    __syncthreads();
    int row = blockIdx.x * blockDim.x + threadIdx.x;
    if (row >= n) return;
    const float4* xr4 = (const float4*)(g_x + (size_t)row * DD);
    unsigned long long acc[32];
#pragma unroll
    for (int o = 0; o < 32; o++) acc[o] = pack2(bias[2 * o], bias[2 * o + 1]);
#pragma unroll
    for (int c = 0; c < 4; c++) {
        float4 v0 = xr4[c * 4 + 0], v1 = xr4[c * 4 + 1];
        float4 v2 = xr4[c * 4 + 2], v3 = xr4[c * 4 + 3];
        float xv[16] = {v0.x, v0.y, v0.z, v0.w, v1.x, v1.y, v1.z, v1.w,
                        v2.x, v2.y, v2.z, v2.w, v3.x, v3.y, v3.z, v3.w};
#pragma unroll
        for (int ii = 0; ii < 16; ii++) {
            int i = c * 16 + ii;
            unsigned long long xv2 = pack2(xv[ii], xv[ii]);
            const ulonglong2* wt4 = (const ulonglong2*)&Wt[i][0];
#pragma unroll
            for (int o = 0; o < 16; o++) {
                ulonglong2 w2 = wt4[o];
                acc[o * 2 + 0] = ffma2(xv2, w2.x, acc[o * 2 + 0]);
                acc[o * 2 + 1] = ffma2(xv2, w2.y, acc[o * 2 + 1]);
            }
        }
    }
    float4* mr4 = (float4*)(g_msg + (size_t)row * DD);
#pragma unroll
    for (int c = 0; c < 16; c++) {
        float a0, a1, a2, a3;
        unpack2(acc[c * 2 + 0], a0, a1);
        unpack2(acc[c * 2 + 1], a2, a3);
        float4 w;
        w.x = RELU(a0); w.y = RELU(a1); w.z = RELU(a2); w.w = RELU(a3);
        mr4[c] = w;
    }
}

// layer-2: y = relu(aggr @ Ua^T + x2part[combo]); fused score
__global__ void __launch_bounds__(128)
k_gemmcat2(const float* __restrict__ U, const float* __restrict__ p, int n) {
    __shared__ __align__(16) float Ut[64][64];
    __shared__ __align__(16) float x2p[32][64];
    __shared__ float ps[64];
    __shared__ float pinv;
    for (int t = threadIdx.x; t < 64 * 64; t += blockDim.x) {
        int o = t >> 6, i = t & 63;
        Ut[i][o] = U[o * 128 + i];
    }
    for (int t = threadIdx.x; t < 32 * 64; t += blockDim.x)
        x2p[t >> 6][t & 63] = g_x2part[t];
    if (threadIdx.x < 64) ps[threadIdx.x] = p[threadIdx.x];
    __syncthreads();
    if (threadIdx.x == 0) {
        float s = 0.f;
        for (int i = 0; i < 64; i++) s += ps[i] * ps[i];
        pinv = 1.0f / sqrtf(s);
    }
    __syncthreads();
    int row = blockIdx.x * blockDim.x + threadIdx.x;
    if (row >= n) return;
    int cmb = g_combo2[row];
    const float4* ar4 = (const float4*)(g_aggr + (size_t)row * DD);
    const unsigned long long* xp2 = (const unsigned long long*)&x2p[cmb][0];
    unsigned long long acc[32];
#pragma unroll
    for (int o = 0; o < 32; o++) acc[o] = xp2[o];
#pragma unroll
    for (int c = 0; c < 4; c++) {
        float4 v0 = ar4[c * 4 + 0], v1 = ar4[c * 4 + 1];
        float4 v2 = ar4[c * 4 + 2], v3 = ar4[c * 4 + 3];
        float av[16] = {v0.x, v0.y, v0.z, v0.w, v1.x, v1.y, v1.z, v1.w,
                        v2.x, v2.y, v2.z, v2.w, v3.x, v3.y, v3.z, v3.w};
#pragma unroll
        for (int ii = 0; ii < 16; ii++) {
            int i = c * 16 + ii;
            unsigned long long av2 = pack2(av[ii], av[ii]);
            const ulonglong2* ut4 = (const ulonglong2*)&Ut[i][0];
#pragma unroll
            for (int o = 0; o < 16; o++) {
                ulonglong2 w2 = ut4[o];
                acc[o * 2 + 0] = ffma2(av2, w2.x, acc[o * 2 + 0]);
                acc[o * 2 + 1] = ffma2(av2, w2.y, acc[o * 2 + 1]);
            }
        }
    }
    float4* yr4 = (float4*)(g_y + (size_t)row * DD);
    float sc = 0.f;
#pragma unroll
    for (int c = 0; c < 16; c++) {
        float a0, a1, a2, a3;
        unpack2(acc[c * 2 + 0], a0, a1);
        unpack2(acc[c * 2 + 1], a2, a3);
        float4 w;
        w.x = RELU(a0); w.y = RELU(a1); w.z = RELU(a2); w.w = RELU(a3);
        yr4[c] = w;
        sc = fmaf(w.x, ps[c * 4 + 0], sc);
        sc = fmaf(w.y, ps[c * 4 + 1], sc);
        sc = fmaf(w.z, ps[c * 4 + 2], sc);
        sc = fmaf(w.w, ps[c * 4 + 3], sc);
    }
    g_score[row] = sc * pinv;
}

// layer-3 full concat GEMM + fused score
__global__ void __launch_bounds__(128)
k_gemmcat(const float* __restrict__ U, const float* __restrict__ p, int n) {
    __shared__ __align__(16) float Ut[128][64];
    __shared__ float ps[64];
    __shared__ float pinv;
    for (int t = threadIdx.x; t < 128 * 64; t += blockDim.x) {
        int o = t >> 7, i = t & 127;
        Ut[i][o] = U[t];
    }
    if (threadIdx.x < 64) ps[threadIdx.x] = p[threadIdx.x];
    __syncthreads();
    if (threadIdx.x == 0) {
        float s = 0.f;
        for (int i = 0; i < 64; i++) s += ps[i] * ps[i];
        pinv = 1.0f / sqrtf(s);
    }
    __syncthreads();
    int row = blockIdx.x * blockDim.x + threadIdx.x;
    if (row >= n) return;
    const float4* ar4 = (const float4*)(g_aggr + (size_t)row * DD);
    const float4* xr4 = (const float4*)(g_x   + (size_t)row * DD);
    unsigned long long acc[32];
#pragma unroll
    for (int o = 0; o < 32; o++) acc[o] = 0ull;
#pragma unroll
    for (int c = 0; c < 4; c++) {
        float4 v0 = ar4[c * 4 + 0], v1 = ar4[c * 4 + 1];
        float4 v2 = ar4[c * 4 + 2], v3 = ar4[c * 4 + 3];
        float av[16] = {v0.x, v0.y, v0.z, v0.w, v1.x, v1.y, v1.z, v1.w,
                        v2.x, v2.y, v2.z, v2.w, v3.x, v3.y, v3.z, v3.w};
#pragma unroll
        for (int ii = 0; ii < 16; ii++) {
            int i = c * 16 + ii;
            unsigned long long av2 = pack2(av[ii], av[ii]);
            const ulonglong2* ut4 = (const ulonglong2*)&Ut[i][0];
#pragma unroll
            for (int o = 0; o < 16; o++) {
                ulonglong2 w2 = ut4[o];
                acc[o * 2 + 0] = ffma2(av2, w2.x, acc[o * 2 + 0]);
                acc[o * 2 + 1] = ffma2(av2, w2.y, acc[o * 2 + 1]);
            }
        }
    }
#pragma unroll
    for (int c = 0; c < 4; c++) {
        float4 v0 = xr4[c * 4 + 0], v1 = xr4[c * 4 + 1];
        float4 v2 = xr4[c * 4 + 2], v3 = xr4[c * 4 + 3];
        float xv[16] = {v0.x, v0.y, v0.z, v0.w, v1.x, v1.y, v1.z, v1.w,
                        v2.x, v2.y, v2.z, v2.w, v3.x, v3.y, v3.z, v3.w};
#pragma unroll
        for (int ii = 0; ii < 16; ii++) {
            int i = 64 + c * 16 + ii;
            unsigned long long xv2 = pack2(xv[ii], xv[ii]);
            const ulonglong2* ut4 = (const ulonglong2*)&Ut[i][0];
#pragma unroll
            for (int o = 0; o < 16; o++) {
                ulonglong2 w2 = ut4[o];
                acc[o * 2 + 0] = ffma2(xv2, w2.x, acc[o * 2 + 0]);
                acc[o * 2 + 1] = ffma2(xv2, w2.y, acc[o * 2 + 1]);
            }
        }
    }
    float4* yr4 = (float4*)(g_y + (size_t)row * DD);
    float sc = 0.f;
#pragma unroll
    for (int c = 0; c < 16; c++) {
        float a0, a1, a2, a3;
        unpack2(acc[c * 2 + 0], a0, a1);
        unpack2(acc[c * 2 + 1], a2, a3);
        float4 w;
        w.x = RELU(a0); w.y = RELU(a1); w.z = RELU(a2); w.w = RELU(a3);
        yr4[c] = w;
        sc = fmaf(w.x, ps[c * 4 + 0], sc);
        sc = fmaf(w.y, ps[c * 4 + 1], sc);
        sc = fmaf(w.z, ps[c * 4 + 2], sc);
        sc = fmaf(w.w, ps[c * 4 + 3], sc);
    }
    g_score[row] = sc * pinv;
}

// ---------------- head ------------------------------------------------------------

__global__ void k_mlp(const float* __restrict__ l1W, const float* __restrict__ l1b,
                      const float* __restrict__ l2W, const float* __restrict__ l2b,
                      const float* __restrict__ l3W, const float* __restrict__ l3b,
                      float* __restrict__ out, int out_size) {
    int b = blockIdx.x;
    int o = threadIdx.x;   // 64
    __shared__ float h[128], s1[64], s2[64];
    h[o]      = g_h[b * 128 + o];
    h[o + 64] = g_h[b * 128 + 64 + o];
    __syncthreads();
    float a = l1b[o];
#pragma unroll 8
    for (int i = 0; i < 128; i++) a = fmaf(h[i], l1W[o * 128 + i], a);
    s1[o] = fmaxf(a, 0.f);
    __syncthreads();
    a = l2b[o];
#pragma unroll 8
    for (int i = 0; i < 64; i++) a = fmaf(s1[i], l2W[o * 64 + i], a);
    s2[o] = fmaxf(a, 0.f);
    __syncthreads();
    a = l3b[o];
#pragma unroll 8
    for (int i = 0; i < 64; i++) a = fmaf(s2[i], l3W[o * 64 + i], a);
    out[b * 64 + o] = 1.f / (1.f + expf(-a));
    for (int i = o; i < K3; i += 64) {
        int pos = 8192 + b * K3 + i;
        if (pos < out_size) out[pos] = (float)b;
    }
}

// ---------------- host orchestration ----------------------------------------------

extern "C" void kernel_launch(void* const* d_in, const int* in_sizes, int n_in,
                              void* d_out, int out_size) {
    const int*   x_ids = (const int*)d_in[0];
    const int*   eidx  = (const int*)d_in[1];
    const float* emb   = (const float*)d_in[2];
    const float* W1 = (const float*)d_in[3];
    const float* b1 = (const float*)d_in[4];
    const float* U1 = (const float*)d_in[5];
    const float* p1 = (const float*)d_in[6];
    const float* W2 = (const float*)d_in[7];
    const float* b2 = (const float*)d_in[8];
    const float* U2 = (const float*)d_in[9];
    const float* p2 = (const float*)d_in[10];
    const float* W3 = (const float*)d_in[11];
    const float* b3 = (const float*)d_in[12];
    const float* U3 = (const float*)d_in[13];
    const float* p3 = (const float*)d_in[14];
    const float* l1W = (const float*)d_in[15];
    const float* l1b = (const float*)d_in[16];
    const float* l2W = (const float*)d_in[17];
    const float* l2b = (const float*)d_in[18];
    const float* l3W = (const float*)d_in[19];
    const float* l3b = (const float*)d_in[20];
    float* out = (float*)d_out;

    const int eb = ETOT / 256;
    const int n2 = BGR * K1;   // 104960
    const int n3 = BGR * K2;   // 83968

    // ---- layer 1 ----
    k_zero_mask<<<(NTOT + 255) / 256, 256>>>();
    k_mask1<<<eb, 256>>>(eidx, eidx + ETOT, x_ids);
    k_lut1<<<1, 256>>>(emb, W1, b1, U1, p1, W2, b2, U2);
    k_topk1<<<BGR, 1024>>>(x_ids);
    k_t1<<<EB + BGR + 256 + 512, 256>>>(eidx, eidx + ETOT);

    // ---- layer 2 ----
    k_aggr2<<<(n2 * 32 + 255) / 256, 256>>>(n2);
    k_gemmcat2<<<(n2 + 127) / 128, 128>>>(U2, p2, n2);
    k_topk<<<BGR, 1024>>>(K1, K2, 1);
    k_t2<<<GB2 + EB, 256>>>(n3);                 // gather(n3) + remap2
    k_t3<<<BGR * 2, 256>>>();                    // readout(K2) + scan256
    k_fill<<<eb, 256>>>();

    // ---- layer 3 ----
    k_gemm64<<<(n3 + 127) / 128, 128>>>(W3, b3, n3);
    k_aggr3<<<(n3 * 32 + 255) / 256, 256>>>(n3);
    k_gemmcat<<<(n3 + 127) / 128, 128>>>(U3, p3, n3);
    k_topk<<<BGR, 1024>>>(K2, K3, 0);
    int nk3 = BGR * K3;
    k_gather<<<(nk3 * DD + 255) / 256, 256>>>(nk3);
    k_readout<<<BGR, 256>>>(K3);

    // ---- head ----
    k_mlp<<<BGR, 64>>>(l1W, l1b, l2W, l2b, l3W, l3b, out, out_size);
}